// round 1
// baseline (speedup 1.0000x reference)
#include <cuda_runtime.h>
#include <cstdint>

// ---------------------------------------------------------------------------
// LSTM: T=512 steps, B=64 batch, IN=512, H=1024.
// Phase 1: Gx[t*B+b][g*H+n] = x[t,b,:] @ Wg[H:H+IN, n] + bg[n]   (parallel)
// Phase 2: per step t: pre = Gx + h_{t-1} @ Wg[0:H, :]; gate math; write h,c.
// h-chain lives in the output buffer (row t-1 is h_{t-1}) -> no h hazard.
// Inner loops use packed fma.rn.f32x2 with K-pair-packed accumulators.
// ---------------------------------------------------------------------------

static constexpr int kT  = 512;
static constexpr int kB  = 64;
static constexpr int kIN = 512;
static constexpr int kH  = 1024;
static constexpr int kG  = 4;
static constexpr int kGXW = kG * kH;          // 4096
static constexpr int kBH = kB * kH;           // 65536

typedef unsigned long long ull;

// Scratch (device globals: allocation-free per harness rules).
__device__ float g_gx[(size_t)kT * kB * kGXW];   // 512 MB, rewritten every run
__device__ float g_c[kBH];                        // cell state (zeroed per run)
__device__ float g_h0[kBH];                       // never written -> stays zero

__device__ __forceinline__ void fma2(ull& d, ull a, ull b) {
    asm("fma.rn.f32x2 %0, %1, %2, %0;" : "+l"(d) : "l"(a), "l"(b));
}
__device__ __forceinline__ float redpair(ull v) {
    float2 f = *reinterpret_cast<float2*>(&v);
    return f.x + f.y;
}
__device__ __forceinline__ float sigmoidf_(float x) {
    return 1.0f / (1.0f + __expf(-x));
}

// ---------------------------------------------------------------------------
// zero the cell state (must happen every kernel_launch call)
// ---------------------------------------------------------------------------
__global__ void zero_c_kernel() {
    int i = blockIdx.x * blockDim.x + threadIdx.x;   // grid exactly kBH
    g_c[i] = 0.0f;
}

// ---------------------------------------------------------------------------
// Phase 1: Gx = X @ Wx + b.  M=32768, K=512, N=1024 per gate.
// Block: 256 threads, tile M=128 x N=32 (one gate), K-chunk 32.
// Thread: 4m x 4n outputs, K-pair-packed accumulators (16 x f32x2).
// ---------------------------------------------------------------------------
static constexpr int P1_BM = 128;
static constexpr int P1_BN = 32;
static constexpr int P1_BK = 32;
static constexpr int P1_PAD = 4;

__global__ void __launch_bounds__(256) phase1_kernel(
    const float* __restrict__ x,
    const float* __restrict__ Wf, const float* __restrict__ Wi,
    const float* __restrict__ Wc, const float* __restrict__ Wo,
    const float* __restrict__ bf, const float* __restrict__ bi,
    const float* __restrict__ bc, const float* __restrict__ bo)
{
    __shared__ float As[P1_BM][P1_BK + P1_PAD];   // [m][k]  (k-contiguous)
    __shared__ float Bsm[P1_BK / 2][P1_BN * 2];   // [k2][n*2 + half] k-pair packed

    const int tid  = threadIdx.x;
    const int gate = blockIdx.x >> 5;                  // 0..3
    const int n0   = (blockIdx.x & 31) * P1_BN;        // 0..992
    const int m0   = blockIdx.y * P1_BM;

    const float* W    = (gate == 0) ? Wf : (gate == 1) ? Wi : (gate == 2) ? Wc : Wo;
    const float* bias = (gate == 0) ? bf : (gate == 1) ? bi : (gate == 2) ? bc : bo;

    const int ng = tid & 7;    // n-group: cols 4*ng..4*ng+3
    const int mg = tid >> 3;   // m-group: rows 4*mg..4*mg+3

    ull acc[4][4];
#pragma unroll
    for (int i = 0; i < 4; i++)
#pragma unroll
        for (int j = 0; j < 4; j++) acc[i][j] = 0ull;

    float4 pa[4];
    float4 pb;

    // prefetch chunk 0
    {
        const int kc = 0;
#pragma unroll
        for (int r = 0; r < 4; r++) {
            int idx = tid + r * 256;
            int m = idx >> 3, fk = idx & 7;
            pa[r] = *reinterpret_cast<const float4*>(&x[(size_t)(m0 + m) * kIN + kc + 4 * fk]);
        }
        int kk = tid >> 3, fn = tid & 7;
        pb = *reinterpret_cast<const float4*>(&W[(size_t)(kH + kc + kk) * kH + n0 + 4 * fn]);
    }

    const int NCH = kIN / P1_BK;   // 16
    for (int c = 0; c < NCH; ++c) {
        __syncthreads();
        // commit prefetched tile to smem
#pragma unroll
        for (int r = 0; r < 4; r++) {
            int idx = tid + r * 256;
            int m = idx >> 3, fk = idx & 7;
            *reinterpret_cast<float4*>(&As[m][4 * fk]) = pa[r];
        }
        {
            int kk = tid >> 3, fn = tid & 7;
            float* brow = &Bsm[kk >> 1][0];
            int half = kk & 1;
            brow[(4 * fn + 0) * 2 + half] = pb.x;
            brow[(4 * fn + 1) * 2 + half] = pb.y;
            brow[(4 * fn + 2) * 2 + half] = pb.z;
            brow[(4 * fn + 3) * 2 + half] = pb.w;
        }
        __syncthreads();
        // prefetch next chunk (hidden under compute)
        if (c + 1 < NCH) {
            int kc = (c + 1) * P1_BK;
#pragma unroll
            for (int r = 0; r < 4; r++) {
                int idx = tid + r * 256;
                int m = idx >> 3, fk = idx & 7;
                pa[r] = *reinterpret_cast<const float4*>(&x[(size_t)(m0 + m) * kIN + kc + 4 * fk]);
            }
            int kk = tid >> 3, fn = tid & 7;
            pb = *reinterpret_cast<const float4*>(&W[(size_t)(kH + kc + kk) * kH + n0 + 4 * fn]);
        }
        // compute 16 k-pairs
#pragma unroll
        for (int k2 = 0; k2 < P1_BK / 2; ++k2) {
            ull a[4];
#pragma unroll
            for (int i = 0; i < 4; i++)
                a[i] = *reinterpret_cast<const ull*>(&As[4 * mg + i][2 * k2]);
            float4 bv0 = *reinterpret_cast<const float4*>(&Bsm[k2][(4 * ng) * 2]);
            float4 bv1 = *reinterpret_cast<const float4*>(&Bsm[k2][(4 * ng + 2) * 2]);
            ull b0 = reinterpret_cast<ull*>(&bv0)[0];
            ull b1 = reinterpret_cast<ull*>(&bv0)[1];
            ull b2 = reinterpret_cast<ull*>(&bv1)[0];
            ull b3 = reinterpret_cast<ull*>(&bv1)[1];
#pragma unroll
            for (int i = 0; i < 4; i++) {
                fma2(acc[i][0], a[i], b0);
                fma2(acc[i][1], a[i], b1);
                fma2(acc[i][2], a[i], b2);
                fma2(acc[i][3], a[i], b3);
            }
        }
    }

    // epilogue: reduce pairs, add bias, store
    float4 bb = *reinterpret_cast<const float4*>(&bias[n0 + 4 * ng]);
#pragma unroll
    for (int i = 0; i < 4; i++) {
        int m = m0 + 4 * mg + i;
        float4 o;
        o.x = redpair(acc[i][0]) + bb.x;
        o.y = redpair(acc[i][1]) + bb.y;
        o.z = redpair(acc[i][2]) + bb.z;
        o.w = redpair(acc[i][3]) + bb.w;
        *reinterpret_cast<float4*>(&g_gx[(size_t)m * kGXW + gate * kH + n0 + 4 * ng]) = o;
    }
}

// ---------------------------------------------------------------------------
// Phase 2 step kernel: pre = h_{t-1} @ Wh (+Gx), gate math, update c, write h.
// Grid: 128 blocks (8 cols of H per block, all 4 gates fused so the update
// can happen in-block). Block: 256 threads, outputs 64b x 32vn.
// Thread: 4b x 2vn, K-pair-packed accumulators.
// ---------------------------------------------------------------------------
static constexpr int S_BN = 8;    // columns per gate per block
static constexpr int S_VN = 32;   // 4 gates * 8
static constexpr int S_BK = 32;
static constexpr int S_PAD = 4;

__global__ void __launch_bounds__(256) step_kernel(
    int t, float* __restrict__ out,
    const float* __restrict__ Wf, const float* __restrict__ Wi,
    const float* __restrict__ Wc, const float* __restrict__ Wo)
{
    __shared__ float As[kB][S_BK + S_PAD];     // 64 x 36 (h tile, k-contiguous)
    __shared__ float Bsm[S_BK / 2][S_VN * 2];  // 16 x 64 (k-pair packed weights)
    __shared__ float pre_s[kB][S_VN];          // gate pre-activations for update

    const int tid = threadIdx.x;
    const int n0  = blockIdx.x * S_BN;

    const float* hprev = (t == 0) ? g_h0 : (out + (size_t)(t - 1) * kBH);

    const int txn = tid & 15;   // vn pair group: vn = 2*txn, 2*txn+1
    const int tyb = tid >> 4;   // b group: rows 4*tyb..4*tyb+3

    ull acc[4][2];
#pragma unroll
    for (int i = 0; i < 4; i++) { acc[i][0] = 0ull; acc[i][1] = 0ull; }

    // B loader mapping: 4 gates x 32 k x 2 float4-slots = 256 loads, 1/thread
    const int lg = tid >> 6;          // gate
    const int lk = (tid >> 1) & 31;   // k within chunk
    const int lj = tid & 1;           // col slot: 4*lj..4*lj+3
    const float* Wl = (lg == 0) ? Wf : (lg == 1) ? Wi : (lg == 2) ? Wc : Wo;

    float4 pa[2];
    float4 pb;
    {
#pragma unroll
        for (int r = 0; r < 2; r++) {
            int idx = tid + r * 256;
            int b = idx >> 3, fk = idx & 7;
            pa[r] = *reinterpret_cast<const float4*>(&hprev[(size_t)b * kH + 4 * fk]);
        }
        pb = *reinterpret_cast<const float4*>(&Wl[(size_t)lk * kH + n0 + 4 * lj]);
    }

    const int NCH = kH / S_BK;   // 32
    for (int c = 0; c < NCH; ++c) {
        __syncthreads();
#pragma unroll
        for (int r = 0; r < 2; r++) {
            int idx = tid + r * 256;
            int b = idx >> 3, fk = idx & 7;
            *reinterpret_cast<float4*>(&As[b][4 * fk]) = pa[r];
        }
        {
            float* brow = &Bsm[lk >> 1][0];
            int half = lk & 1;
            int vb = lg * 8 + 4 * lj;
            brow[(vb + 0) * 2 + half] = pb.x;
            brow[(vb + 1) * 2 + half] = pb.y;
            brow[(vb + 2) * 2 + half] = pb.z;
            brow[(vb + 3) * 2 + half] = pb.w;
        }
        __syncthreads();
        if (c + 1 < NCH) {
            int kc = (c + 1) * S_BK;
#pragma unroll
            for (int r = 0; r < 2; r++) {
                int idx = tid + r * 256;
                int b = idx >> 3, fk = idx & 7;
                pa[r] = *reinterpret_cast<const float4*>(&hprev[(size_t)b * kH + kc + 4 * fk]);
            }
            pb = *reinterpret_cast<const float4*>(&Wl[(size_t)(kc + lk) * kH + n0 + 4 * lj]);
        }
#pragma unroll
        for (int k2 = 0; k2 < S_BK / 2; ++k2) {
            ull a[4];
#pragma unroll
            for (int i = 0; i < 4; i++)
                a[i] = *reinterpret_cast<const ull*>(&As[4 * tyb + i][2 * k2]);
            float4 bv = *reinterpret_cast<const float4*>(&Bsm[k2][4 * txn]);
            ull b0 = reinterpret_cast<ull*>(&bv)[0];
            ull b1 = reinterpret_cast<ull*>(&bv)[1];
#pragma unroll
            for (int i = 0; i < 4; i++) {
                fma2(acc[i][0], a[i], b0);
                fma2(acc[i][1], a[i], b1);
            }
        }
    }

    // reduce pairs, add Gx, publish pre-activations for the block
    {
        const float* gx = &g_gx[(size_t)t * ((size_t)kB * kGXW)];
#pragma unroll
        for (int i = 0; i < 4; i++) {
            int b = 4 * tyb + i;
#pragma unroll
            for (int j = 0; j < 2; j++) {
                int vn = 2 * txn + j;
                int gate = vn >> 3;
                int col = vn & 7;
                float p = redpair(acc[i][j]) +
                          gx[(size_t)b * kGXW + gate * kH + n0 + col];
                pre_s[b][vn] = p;
            }
        }
    }
    __syncthreads();

    // elementwise LSTM update: 64b x 8cols = 512 items, 2 per thread
#pragma unroll
    for (int r = 0; r < 2; r++) {
        int idx = tid + r * 256;
        int b = idx >> 3;
        int j = idx & 7;
        float f  = sigmoidf_(pre_s[b][j]);
        float ii = sigmoidf_(pre_s[b][8 + j]);
        float gg = tanhf(pre_s[b][16 + j]);
        float oo = sigmoidf_(pre_s[b][24 + j]);
        int cidx = b * kH + n0 + j;
        float cnew = f * g_c[cidx] + ii * gg;
        g_c[cidx] = cnew;
        float h = oo * tanhf(cnew);
        out[(size_t)t * kBH + cidx] = h;
        if (t == kT - 1) {
            out[(size_t)kT * kBH + cidx] = h;            // final h tail
            out[(size_t)kT * kBH + kBH + cidx] = cnew;   // final c tail
        }
    }
}

// ---------------------------------------------------------------------------
// Launch: zero c, phase-1 GEMM, 512 sequential fused step kernels.
// All on the default stream (graph-capturable, allocation-free).
// ---------------------------------------------------------------------------
extern "C" void kernel_launch(void* const* d_in, const int* in_sizes, int n_in,
                              void* d_out, int out_size)
{
    const float* x  = (const float*)d_in[0];
    const float* Wf = (const float*)d_in[1];
    const float* bf = (const float*)d_in[2];
    const float* Wi = (const float*)d_in[3];
    const float* bi = (const float*)d_in[4];
    const float* Wc = (const float*)d_in[5];
    const float* bc = (const float*)d_in[6];
    const float* Wo = (const float*)d_in[7];
    const float* bo = (const float*)d_in[8];
    float* out = (float*)d_out;

    zero_c_kernel<<<kBH / 256, 256>>>();

    dim3 g1(128, kT * kB / P1_BM);   // 128 x 256 blocks
    phase1_kernel<<<g1, 256>>>(x, Wf, Wi, Wc, Wo, bf, bi, bc, bo);

    for (int t = 0; t < kT; ++t) {
        step_kernel<<<kH / S_BN, 256>>>(t, out, Wf, Wi, Wc, Wo);
    }
}